// round 11
// baseline (speedup 1.0000x reference)
#include <cuda_runtime.h>
#include <cuda_bf16.h>
#include <math.h>
#include <stdint.h>

// ---------------- problem constants ----------------
constexpr int B_ = 4096;
constexpr int D_ = 1024;
constexpr int T_ = 768;
constexpr int C_ = 16;
constexpr int HD_ = 256;
constexpr float CURV = 0.05f;
constexpr float EPSF = 1e-8f;
constexpr float SCF = 0.22360679774997896f;
constexpr float ASINH_MAX = 11.090354888959125f;

constexpr size_t OFF_LOSS   = (size_t)B_ * C_;
constexpr size_t OFF_OH     = OFF_LOSS + 1;
constexpr size_t OFF_FH     = OFF_OH  + (size_t)B_ * D_;
constexpr size_t OFF_OEU    = OFF_FH  + (size_t)B_ * D_;
constexpr size_t OFF_FEU    = OFF_OEU + (size_t)B_ * D_;

// ---------------- device scratch ----------------
__device__ float g_gf   [(size_t)B_ * 4 * D_];
__device__ float g_qkv  [(size_t)B_ * 4 * 3 * D_];
__device__ float g_alin [(size_t)B_ * 4 * D_];
__device__ float g_oflin[(size_t)B_ * D_];
__device__ float g_fflin[(size_t)B_ * D_];
__device__ float g_peno [B_];
__device__ float g_penf [B_];
__device__ float g_clsx [C_ * D_];
__device__ float g_clsap[C_ * D_];
__device__ float g_clsx2[C_];
__device__ float g_clsax[C_];
__device__ float g_clsan[C_];
__device__ float g_clskk[C_];

__device__ __align__(16) __nv_bfloat16 g_gfh [(size_t)B_ * 4 * D_];
__device__ __align__(16) __nv_bfloat16 g_gfl [(size_t)B_ * 4 * D_];
__device__ __align__(16) __nv_bfloat16 g_aoh [(size_t)B_ * 4 * D_];
__device__ __align__(16) __nv_bfloat16 g_aol [(size_t)B_ * 4 * D_];
__device__ __align__(16) __nv_bfloat16 g_wih [(size_t)3 * D_ * D_];
__device__ __align__(16) __nv_bfloat16 g_wil [(size_t)3 * D_ * D_];
__device__ __align__(16) __nv_bfloat16 g_woh [(size_t)D_ * D_];
__device__ __align__(16) __nv_bfloat16 g_wol [(size_t)D_ * D_];
__device__ __align__(16) __nv_bfloat16 g_toh [(size_t)D_ * T_];
__device__ __align__(16) __nv_bfloat16 g_tol [(size_t)D_ * T_];
__device__ __align__(16) __nv_bfloat16 g_tfh [(size_t)D_ * T_];
__device__ __align__(16) __nv_bfloat16 g_tfl [(size_t)D_ * T_];
__device__ __align__(16) __nv_bfloat16 g_ordh[(size_t)B_ * T_];
__device__ __align__(16) __nv_bfloat16 g_ordl[(size_t)B_ * T_];
__device__ __align__(16) __nv_bfloat16 g_famh[(size_t)B_ * T_];
__device__ __align__(16) __nv_bfloat16 g_faml[(size_t)B_ * T_];

// ================= PTX helpers (baseline PTX only) =================
__device__ __forceinline__ uint32_t smem_to_u32(const void* p) {
    uint32_t a;
    asm("{ .reg .u64 t; cvta.to.shared.u64 t, %1; cvt.u32.u64 %0, t; }" : "=r"(a) : "l"(p));
    return a;
}
#define SWIZ128(o) ((o) ^ (((o) >> 3) & 0x70))

#define CP_ASYNC16(dst, src) \
    asm volatile("cp.async.cg.shared.global [%0], [%1], 16;" :: "r"(dst), "l"(src) : "memory")
#define CP_COMMIT() asm volatile("cp.async.commit_group;" ::: "memory")
#define CP_WAIT1()  asm volatile("cp.async.wait_group 1;" ::: "memory")
#define CP_WAIT0()  asm volatile("cp.async.wait_group 0;" ::: "memory")

#define LDMATRIX_X4(r0, r1, r2, r3, addr) \
    asm volatile("ldmatrix.sync.aligned.m8n8.x4.shared.b16 {%0,%1,%2,%3}, [%4];" \
                 : "=r"(r0), "=r"(r1), "=r"(r2), "=r"(r3) : "r"(addr))

#define MMA_BF16(c0, c1, c2, c3, a0, a1, a2, a3, b0, b1) \
    asm volatile("mma.sync.aligned.m16n8k16.row.col.f32.bf16.bf16.f32 " \
                 "{%0,%1,%2,%3}, {%4,%5,%6,%7}, {%8,%9}, {%0,%1,%2,%3};" \
                 : "+f"(c0), "+f"(c1), "+f"(c2), "+f"(c3) \
                 : "r"(a0), "r"(a1), "r"(a2), "r"(a3), "r"(b0), "r"(b1))

// ================= fused split-bf16 tensor-core GEMM =================
// C[M,N] = (Ahi+Alo)[M,K] @ ((Bhi+Blo)[N,K])^T + bias[N]   (lo*lo dropped)
// Per K-chunk: load A_hi/A_lo/B_hi/B_lo once; 3 MMA passes on resident tiles.
constexpr int BM = 128, BN = 256, KC = 64;
constexpr int ATB = BM * 128;               // 16 KB per A tile (KC=64 bf16 rows)
constexpr int BTB = BN * 128;               // 32 KB per B tile
constexpr int STAGE_B = 2 * ATB + 2 * BTB;  // 96 KB per stage
constexpr int GEMM_SMEM = 2 * STAGE_B;      // 192 KB double-buffered

__global__ void __launch_bounds__(512, 1)
gemm_bf16x3(const __nv_bfloat16* __restrict__ Ahi, const __nv_bfloat16* __restrict__ Alo,
            const __nv_bfloat16* __restrict__ Bhi, const __nv_bfloat16* __restrict__ Blo,
            const float* __restrict__ bias, float* __restrict__ Cm,
            int M, int N, int K) {
    extern __shared__ char smem[];
    uint32_t sb = smem_to_u32(smem);
    int tid = threadIdx.x;
    int wid = tid >> 5;
    int lane = tid & 31;
    int wm = wid & 1;       // 2 warps in M -> 64 rows
    int wn = wid >> 1;      // 8 warps in N -> 32 cols
    int m0 = blockIdx.y * BM;
    int n0 = blockIdx.x * BN;
    int nk = K / KC;

    float acc[4][4][4];
#pragma unroll
    for (int i = 0; i < 4; i++)
#pragma unroll
        for (int j = 0; j < 4; j++)
#pragma unroll
            for (int t = 0; t < 4; t++) acc[i][j][t] = 0.f;

    int lc = tid & 7;        // 16B chunk within 128B row
    int lr = tid >> 3;       // base row (0..63)

    auto load_tile = [&](int k, int stage) {
        int kk = k * KC;
        const __nv_bfloat16* Ah = Ahi + (size_t)m0 * K + kk;
        const __nv_bfloat16* Al = Alo + (size_t)m0 * K + kk;
        const __nv_bfloat16* Bh = Bhi + (size_t)n0 * K + kk;
        const __nv_bfloat16* Bl = Blo + (size_t)n0 * K + kk;
        uint32_t s = sb + stage * STAGE_B;
#pragma unroll
        for (int j = 0; j < 2; j++) {
            int row = lr + j * 64;
            uint32_t off = SWIZ128(row * 128 + lc * 16);
            CP_ASYNC16(s + off,       Ah + (size_t)row * K + lc * 8);
            CP_ASYNC16(s + ATB + off, Al + (size_t)row * K + lc * 8);
        }
#pragma unroll
        for (int j = 0; j < 4; j++) {
            int row = lr + j * 64;
            uint32_t off = SWIZ128(row * 128 + lc * 16);
            CP_ASYNC16(s + 2 * ATB + off,       Bh + (size_t)row * K + lc * 8);
            CP_ASYNC16(s + 2 * ATB + BTB + off, Bl + (size_t)row * K + lc * 8);
        }
        CP_COMMIT();
    };

    load_tile(0, 0);

    for (int k = 0; k < nk; k++) {
        bool more = (k + 1 < nk);
        if (more) load_tile(k + 1, (k + 1) & 1);
        if (more) CP_WAIT1(); else CP_WAIT0();
        __syncthreads();

        uint32_t s = sb + (k & 1) * STAGE_B;
#pragma unroll
        for (int p = 0; p < 3; p++) {   // hi*hi, lo*hi, hi*lo
            uint32_t sA = s + (p == 1 ? ATB : 0);
            uint32_t sB = s + 2 * ATB + (p == 2 ? BTB : 0);
#pragma unroll
            for (int ks = 0; ks < 4; ks++) {
                int kb = ks * 32;
                uint32_t a[4][4];
#pragma unroll
                for (int mi = 0; mi < 4; mi++) {
                    int row = wm * 64 + mi * 16 + (lane & 15);
                    uint32_t off = SWIZ128(row * 128 + kb + (lane >> 4) * 16);
                    LDMATRIX_X4(a[mi][0], a[mi][1], a[mi][2], a[mi][3], sA + off);
                }
                uint32_t bq[2][4];
#pragma unroll
                for (int nj2 = 0; nj2 < 2; nj2++) {
                    int g = lane >> 3;
                    int row = wn * 32 + nj2 * 16 + (g >> 1) * 8 + (lane & 7);
                    uint32_t off = SWIZ128(row * 128 + kb + (g & 1) * 16);
                    LDMATRIX_X4(bq[nj2][0], bq[nj2][1], bq[nj2][2], bq[nj2][3], sB + off);
                }
#pragma unroll
                for (int mi = 0; mi < 4; mi++)
#pragma unroll
                    for (int nj = 0; nj < 4; nj++) {
                        uint32_t b0 = bq[nj >> 1][(nj & 1) * 2 + 0];
                        uint32_t b1 = bq[nj >> 1][(nj & 1) * 2 + 1];
                        MMA_BF16(acc[mi][nj][0], acc[mi][nj][1], acc[mi][nj][2], acc[mi][nj][3],
                                 a[mi][0], a[mi][1], a[mi][2], a[mi][3], b0, b1);
                    }
            }
        }
        __syncthreads();
    }

    // epilogue: registers -> global, add bias
#pragma unroll
    for (int mi = 0; mi < 4; mi++) {
        int m = m0 + wm * 64 + mi * 16 + (lane >> 2);
#pragma unroll
        for (int nj = 0; nj < 4; nj++) {
            int n = n0 + wn * 32 + nj * 8 + (lane & 3) * 2;
            float2 bv = *(const float2*)(bias + n);
            float2 o0 = { acc[mi][nj][0] + bv.x, acc[mi][nj][1] + bv.y };
            float2 o1 = { acc[mi][nj][2] + bv.x, acc[mi][nj][3] + bv.y };
            *(float2*)(Cm + (size_t)m * N + n)       = o0;
            *(float2*)(Cm + (size_t)(m + 8) * N + n) = o1;
        }
    }
}

// ================= helpers =================
__device__ __forceinline__ float blockReduceSum(float v) {
    __shared__ float sh[33];
    int lane = threadIdx.x & 31;
    int wid  = threadIdx.x >> 5;
    __syncthreads();
#pragma unroll
    for (int o = 16; o; o >>= 1) v += __shfl_xor_sync(0xffffffffu, v, o);
    if (lane == 0) sh[wid] = v;
    __syncthreads();
    if (wid == 0) {
        int nw = (blockDim.x + 31) >> 5;
        float x = (lane < nw) ? sh[lane] : 0.f;
#pragma unroll
        for (int o = 16; o; o >>= 1) x += __shfl_xor_sync(0xffffffffu, x, o);
        if (lane == 0) sh[32] = x;
    }
    __syncthreads();
    return sh[32];
}
__device__ __forceinline__ float artanh_f(float x) {
    x = fminf(fmaxf(x, -1.f + 1e-5f), 1.f - 1e-5f);
    return 0.5f * (log1pf(x) - log1pf(-x));
}
__device__ __forceinline__ float plog_scale(float n) {
    n = fmaxf(n, 1e-15f);
    return artanh_f(SCF * n) / (n * SCF);
}
__device__ __forceinline__ float lexp_scale(float norm) {
    float rc = SCF * norm;
    float si = fminf(fmaxf(rc, EPSF), ASINH_MAX);
    return sinhf(si) / fmaxf(rc, EPSF);
}
__device__ __forceinline__ float oxy_angle_s(float xx, float nx, float xy, float yy) {
    float xt = sqrtf(1.f / CURV + xx);
    float yt = sqrtf(1.f / CURV + yy);
    float cxyl = CURV * (xy - xt * yt);
    float num = yt + cxyl * xt;
    float den = sqrtf(fmaxf(cxyl * cxyl - 1.f, EPSF));
    float ai = num / (nx * den + EPSF);
    ai = fminf(fmaxf(ai, -1.f + EPSF), 1.f - EPSF);
    return acosf(ai);
}
__device__ __forceinline__ float half_aperture_s(float nx) {
    float si = 0.2f / (nx * SCF + EPSF);
    si = fminf(fmaxf(si, -1.f + EPSF), 1.f - EPSF);
    return asinf(si);
}
__device__ __forceinline__ void bf16_split(float v, __nv_bfloat16* hi, __nv_bfloat16* lo, size_t i) {
    __nv_bfloat16 h = __float2bfloat16(v);
    hi[i] = h;
    lo[i] = __float2bfloat16(v - __bfloat162float(h));
}

// ---------------- prep_gf ----------------
__global__ void prep_gf(const float* __restrict__ ohyp, const float* __restrict__ fhyp,
                        const float* __restrict__ oeuc, const float* __restrict__ feuc) {
    int b = blockIdx.x;
    const float* xo = ohyp + (size_t)b * D_;
    const float* xf = fhyp + (size_t)b * D_;
    float so = 0.f, sf = 0.f;
    for (int i = threadIdx.x; i < D_; i += blockDim.x) {
        float a = xo[i]; so += a * a;
        float c = xf[i]; sf += c * c;
    }
    so = blockReduceSum(so);
    sf = blockReduceSum(sf);
    float to = plog_scale(sqrtf(so));
    float tf = plog_scale(sqrtf(sf));
    size_t rb = (size_t)b * 4 * D_;
    float* g0 = g_gf + rb;
    for (int i = threadIdx.x; i < D_; i += blockDim.x) {
        float v0 = xo[i] * to;
        float v1 = xf[i] * tf;
        float v2 = oeuc[(size_t)b * D_ + i];
        float v3 = feuc[(size_t)b * D_ + i];
        g0[i] = v0;  g0[D_ + i] = v1;  g0[2 * D_ + i] = v2;  g0[3 * D_ + i] = v3;
        bf16_split(v0, g_gfh, g_gfl, rb + i);
        bf16_split(v1, g_gfh, g_gfl, rb + D_ + i);
        bf16_split(v2, g_gfh, g_gfl, rb + 2 * D_ + i);
        bf16_split(v3, g_gfh, g_gfl, rb + 3 * D_ + i);
    }
}

// ---------------- fp32 -> bf16 hi/lo split ----------------
__global__ void cvt_split(const float* __restrict__ x, __nv_bfloat16* __restrict__ hi,
                          __nv_bfloat16* __restrict__ lo, int n4) {
    int i = blockIdx.x * blockDim.x + threadIdx.x;
    if (i < n4) {
        float4 v = *(const float4*)(x + (size_t)i * 4);
        size_t o = (size_t)i * 4;
        bf16_split(v.x, hi, lo, o + 0);
        bf16_split(v.y, hi, lo, o + 1);
        bf16_split(v.z, hi, lo, o + 2);
        bf16_split(v.w, hi, lo, o + 3);
    }
}

// ---------------- attention (S=4, one warp per head) ----------------
__global__ void attn_kernel() {
    int b = blockIdx.x;
    int hh = threadIdx.x >> 5;
    int lane = threadIdx.x & 31;
    const float* base = g_qkv + (size_t)b * 4 * (3 * D_);
    float s[4][4];
#pragma unroll
    for (int i = 0; i < 4; i++) {
#pragma unroll
        for (int j = 0; j < 4; j++) {
            const float* q = base + i * 3 * D_ + hh * HD_;
            const float* k = base + j * 3 * D_ + D_ + hh * HD_;
            float p = 0.f;
#pragma unroll
            for (int d = 0; d < HD_; d += 32) p += q[d + lane] * k[d + lane];
#pragma unroll
            for (int o = 16; o; o >>= 1) p += __shfl_xor_sync(0xffffffffu, p, o);
            s[i][j] = p * (1.f / 16.f);
        }
    }
    float a[4][4];
#pragma unroll
    for (int i = 0; i < 4; i++) {
        float m = fmaxf(fmaxf(s[i][0], s[i][1]), fmaxf(s[i][2], s[i][3]));
        float e0 = expf(s[i][0] - m), e1 = expf(s[i][1] - m);
        float e2 = expf(s[i][2] - m), e3 = expf(s[i][3] - m);
        float inv = 1.f / (e0 + e1 + e2 + e3);
        a[i][0] = e0 * inv; a[i][1] = e1 * inv; a[i][2] = e2 * inv; a[i][3] = e3 * inv;
    }
#pragma unroll
    for (int i = 0; i < 4; i++) {
        for (int d = lane; d < HD_; d += 32) {
            float acc = 0.f;
#pragma unroll
            for (int j = 0; j < 4; j++)
                acc += a[i][j] * base[j * 3 * D_ + 2 * D_ + hh * HD_ + d];
            bf16_split(acc, g_aoh, g_aol, (size_t)b * 4 * D_ + i * D_ + hh * HD_ + d);
        }
    }
}

// ---------------- residual + LN + l_expmap0 ----------------
__global__ void resid_ln_exp(const float* __restrict__ lnw, const float* __restrict__ lnb,
                             float* __restrict__ out) {
    int r = blockIdx.x;
    int b = r >> 2;
    int i = r & 3;
    const float* x0 = g_gf + (size_t)r * D_;
    const float* x1 = g_alin + (size_t)r * D_;
    float x[4];
    float s = 0.f;
#pragma unroll
    for (int t = 0; t < 4; t++) {
        int idx = threadIdx.x + t * 256;
        float v = x0[idx] + x1[idx];
        x[t] = v; s += v;
    }
    s = blockReduceSum(s);
    float mu = s * (1.f / D_);
    float vv = 0.f;
#pragma unroll
    for (int t = 0; t < 4; t++) { float d = x[t] - mu; vv += d * d; }
    vv = blockReduceSum(vv);
    float rstd = rsqrtf(vv * (1.f / D_) + 1e-5f);
    float y[4];
    float sy2 = 0.f;
#pragma unroll
    for (int t = 0; t < 4; t++) {
        int idx = threadIdx.x + t * 256;
        y[t] = (x[t] - mu) * rstd * lnw[idx] + lnb[idx];
        sy2 += y[t] * y[t];
    }
    if (i >= 2) {
        size_t off = (i == 2 ? OFF_OEU : OFF_FEU) + (size_t)b * D_;
#pragma unroll
        for (int t = 0; t < 4; t++) out[off + threadIdx.x + t * 256] = y[t];
    } else {
        sy2 = blockReduceSum(sy2);
        float sc = lexp_scale(sqrtf(sy2));
        size_t off = (i == 0 ? OFF_OH : OFF_FH) + (size_t)b * D_;
#pragma unroll
        for (int t = 0; t < 4; t++) out[off + threadIdx.x + t * 256] = y[t] * sc;
    }
}

// ---------------- per-row hyperbolic penalties ----------------
__global__ void loss_rows(const float* __restrict__ out) {
    int b = blockIdx.x;
    const float* of = g_oflin + (size_t)b * D_;
    const float* ff = g_fflin + (size_t)b * D_;
    const float* fh = out + OFF_FH + (size_t)b * D_;
    const float* oh = out + OFF_OH + (size_t)b * D_;
    float n2of = 0.f, dof = 0.f, n2fh = 0.f, n2ff = 0.f, dff = 0.f, n2oh = 0.f;
    for (int i = threadIdx.x; i < D_; i += blockDim.x) {
        float a = of[i], c = ff[i], yf = fh[i], yo = oh[i];
        n2of += a * a;  dof += a * yf;  n2fh += yf * yf;
        n2ff += c * c;  dff += c * yo;  n2oh += yo * yo;
    }
    n2of = blockReduceSum(n2of); dof = blockReduceSum(dof); n2fh = blockReduceSum(n2fh);
    n2ff = blockReduceSum(n2ff); dff = blockReduceSum(dff); n2oh = blockReduceSum(n2oh);
    if (threadIdx.x == 0) {
        float no = sqrtf(n2of);
        float so = lexp_scale(no);
        float xx = so * so * n2of, nx = so * no, xy = so * dof;
        float pen_o = fmaxf(oxy_angle_s(xx, nx, xy, n2fh) - half_aperture_s(nx), 0.f);
        float nf = sqrtf(n2ff);
        float sf = lexp_scale(nf);
        float xx2 = sf * sf * n2ff, nx2 = sf * nf, xy2 = sf * dff;
        float pen_f = fmaxf(oxy_angle_s(xx2, nx2, xy2, n2oh) - half_aperture_s(nx2), 0.f);
        g_peno[b] = pen_o;
        g_penf[b] = pen_f;
    }
}

__global__ void loss_reduce(const int* __restrict__ mask, float* __restrict__ out) {
    float so = 0.f, sf = 0.f, sm = 0.f;
    for (int i = threadIdx.x; i < B_; i += blockDim.x) {
        so += g_peno[i];
        float m = (float)mask[i];
        sf += g_penf[i] * m;
        sm += m;
    }
    so = blockReduceSum(so);
    sf = blockReduceSum(sf);
    sm = blockReduceSum(sm);
    if (threadIdx.x == 0) {
        float fam = (sm > 0.f) ? sf / fmaxf(sm, 1.f) : 0.f;
        out[OFF_LOSS] = so * (1.f / B_) + fam;
    }
}

// ---------------- per-class MLR constants ----------------
__global__ void class_prep(const float* __restrict__ mlr_a, const float* __restrict__ mlr_p) {
    for (int c = 0; c < C_; c++) {
        const float* p = mlr_p + (size_t)c * D_;
        const float* a = mlr_a + (size_t)c * D_;
        float n2p = 0.f, n2a = 0.f, dpa = 0.f;
        for (int i = threadIdx.x; i < D_; i += blockDim.x) {
            float pv = p[i], av = a[i];
            n2p += pv * pv; n2a += av * av; dpa += pv * av;
        }
        n2p = blockReduceSum(n2p);
        n2a = blockReduceSum(n2a);
        dpa = blockReduceSum(dpa);
        float n = fmaxf(sqrtf(n2p), 1e-15f);
        float t = tanhf(SCF * n) / (SCF * n);
        float pp2 = t * t * n2p;
        float conf = 1.f - CURV * pp2;
        float anorm = fabsf(conf) * sqrtf(n2a);
        float lam = 2.f / (1.f - CURV * pp2);
        if (threadIdx.x == 0) {
            g_clsx2[c] = pp2;
            g_clsax[c] = -t * conf * dpa;
            g_clsan[c] = anorm;
            g_clskk[c] = lam * anorm / SCF;
        }
        for (int i = threadIdx.x; i < D_; i += blockDim.x) {
            g_clsx[c * D_ + i]  = -t * p[i];
            g_clsap[c * D_ + i] = conf * a[i];
        }
    }
}

// ---------------- logits (closed-form mobius) ----------------
__global__ void logits_kernel(float* __restrict__ out) {
    int b = blockIdx.x;
    const float* oh = out + OFF_OH + (size_t)b * D_;
    float n2 = 0.f;
    float dx[C_], da[C_];
#pragma unroll
    for (int c = 0; c < C_; c++) { dx[c] = 0.f; da[c] = 0.f; }
    for (int i = threadIdx.x; i < D_; i += blockDim.x) {
        float v = oh[i];
        n2 += v * v;
#pragma unroll
        for (int c = 0; c < C_; c++) {
            dx[c] += v * g_clsx[c * D_ + i];
            da[c] += v * g_clsap[c * D_ + i];
        }
    }
    __shared__ float sred[33];
#pragma unroll
    for (int c = 0; c < C_; c++) {
        float r = blockReduceSum(dx[c]);
        if (threadIdx.x == 0) sred[c] = r;
    }
#pragma unroll
    for (int c = 0; c < C_; c++) {
        float r = blockReduceSum(da[c]);
        if (threadIdx.x == 0) sred[C_ + c] = r;
    }
    n2 = blockReduceSum(n2);
    if (threadIdx.x == 0) sred[32] = n2;
    __syncthreads();

    if (threadIdx.x < C_) {
        int c = threadIdx.x;
        float n2o = sred[32];
        float no = sqrtf(n2o);
        float rc1 = SCF * no;
        float t1 = asinhf(rc1) / fmaxf(rc1, EPSF);
        float nu = t1 * no;
        float ncl = fmaxf(nu, 1e-15f);
        float t2 = tanhf(SCF * ncl) / (SCF * ncl);
        float nxv = t2 * nu;
        float maxn = (1.f - 0.004f) / SCF;
        float proj = (nxv > maxn) ? maxn / fmaxf(nxv, 1e-15f) : 1.f;
        float g = t1 * t2 * proj;

        float y2 = g * g * n2o;
        float xy = g * sred[c];
        float ay = g * sred[C_ + c];
        float x2 = g_clsx2[c];
        float alpha = 1.f + 2.f * CURV * xy + CURV * y2;
        float beta  = 1.f - CURV * x2;
        float den0  = 1.f + 2.f * CURV * xy + CURV * CURV * x2 * y2 + 1e-5f;
        float mobdot = (alpha * g_clsax[c] + beta * ay) / den0;
        float mob2   = (alpha * alpha * x2 + 2.f * alpha * beta * xy + beta * beta * y2) / (den0 * den0);
        float num = 2.f * SCF * mobdot;
        float den = g_clsan[c] * (1.f - CURV * mob2);
        out[(size_t)b * C_ + c] = g_clskk[c] * asinhf(num / den);
    }
}

// ---------------- launch ----------------
extern "C" void kernel_launch(void* const* d_in, const int* in_sizes, int n_in,
                              void* d_out, int out_size) {
    const float* order_hyp  = (const float*)d_in[0];
    const float* family_hyp = (const float*)d_in[1];
    const float* order_euc  = (const float*)d_in[2];
    const float* family_euc = (const float*)d_in[3];
    const float* order      = (const float*)d_in[4];
    const float* family     = (const float*)d_in[5];
    const int*   mask       = (const int*)d_in[6];
    const float* in_proj_w  = (const float*)d_in[7];
    const float* in_proj_b  = (const float*)d_in[8];
    const float* out_proj_w = (const float*)d_in[9];
    const float* out_proj_b = (const float*)d_in[10];
    const float* ln_w       = (const float*)d_in[11];
    const float* ln_b       = (const float*)d_in[12];
    const float* to_w       = (const float*)d_in[13];
    const float* to_b       = (const float*)d_in[14];
    const float* tf_w       = (const float*)d_in[15];
    const float* tf_b       = (const float*)d_in[16];
    const float* mlr_a      = (const float*)d_in[17];
    const float* mlr_p      = (const float*)d_in[18];
    float* out = (float*)d_out;

    float* qkv  = nullptr; cudaGetSymbolAddress((void**)&qkv,  g_qkv);
    float* alin = nullptr; cudaGetSymbolAddress((void**)&alin, g_alin);
    float* ofl  = nullptr; cudaGetSymbolAddress((void**)&ofl,  g_oflin);
    float* ffl  = nullptr; cudaGetSymbolAddress((void**)&ffl,  g_fflin);
    __nv_bfloat16 *gfh, *gfl, *aoh, *aol, *wih, *wil, *woh, *wol;
    __nv_bfloat16 *toh, *tol, *tfh, *tfl, *ordh, *ordl, *famh, *faml;
    cudaGetSymbolAddress((void**)&gfh,  g_gfh);  cudaGetSymbolAddress((void**)&gfl,  g_gfl);
    cudaGetSymbolAddress((void**)&aoh,  g_aoh);  cudaGetSymbolAddress((void**)&aol,  g_aol);
    cudaGetSymbolAddress((void**)&wih,  g_wih);  cudaGetSymbolAddress((void**)&wil,  g_wil);
    cudaGetSymbolAddress((void**)&woh,  g_woh);  cudaGetSymbolAddress((void**)&wol,  g_wol);
    cudaGetSymbolAddress((void**)&toh,  g_toh);  cudaGetSymbolAddress((void**)&tol,  g_tol);
    cudaGetSymbolAddress((void**)&tfh,  g_tfh);  cudaGetSymbolAddress((void**)&tfl,  g_tfl);
    cudaGetSymbolAddress((void**)&ordh, g_ordh); cudaGetSymbolAddress((void**)&ordl, g_ordl);
    cudaGetSymbolAddress((void**)&famh, g_famh); cudaGetSymbolAddress((void**)&faml, g_faml);

    cudaFuncSetAttribute(gemm_bf16x3, cudaFuncAttributeMaxDynamicSharedMemorySize, GEMM_SMEM);

    auto splitN = [&](const float* src, __nv_bfloat16* hi, __nv_bfloat16* lo, size_t n) {
        int n4 = (int)(n / 4);
        cvt_split<<<(n4 + 255) / 256, 256>>>(src, hi, lo, n4);
    };
    splitN(in_proj_w,  wih,  wil,  (size_t)3 * D_ * D_);
    splitN(out_proj_w, woh,  wol,  (size_t)D_ * D_);
    splitN(to_w,       toh,  tol,  (size_t)D_ * T_);
    splitN(tf_w,       tfh,  tfl,  (size_t)D_ * T_);
    splitN(order,      ordh, ordl, (size_t)B_ * T_);
    splitN(family,     famh, faml, (size_t)B_ * T_);

    // 1. build gf (fp32 + bf16 split)
    prep_gf<<<B_, 256>>>(order_hyp, family_hyp, order_euc, family_euc);
    // 2. qkv = gf @ Win^T + b  [16384 x 3072, K=1024]
    gemm_bf16x3<<<dim3(3 * D_ / BN, B_ * 4 / BM), 512, GEMM_SMEM>>>(
        gfh, gfl, wih, wil, in_proj_b, qkv, B_ * 4, 3 * D_, D_);
    // 3. attention (writes bf16-split attn output)
    attn_kernel<<<B_, 128>>>();
    // 4. out-proj [16384 x 1024, K=1024]
    gemm_bf16x3<<<dim3(D_ / BN, B_ * 4 / BM), 512, GEMM_SMEM>>>(
        aoh, aol, woh, wol, out_proj_b, alin, B_ * 4, D_, D_);
    // 5. residual + LN + l_expmap0 -> outputs
    resid_ln_exp<<<B_ * 4, 256>>>(ln_w, ln_b, out);
    // 6/7. feature projections [4096 x 1024, K=768]
    gemm_bf16x3<<<dim3(D_ / BN, B_ / BM), 512, GEMM_SMEM>>>(
        ordh, ordl, toh, tol, to_b, ofl, B_, D_, T_);
    gemm_bf16x3<<<dim3(D_ / BN, B_ / BM), 512, GEMM_SMEM>>>(
        famh, faml, tfh, tfl, tf_b, ffl, B_, D_, T_);
    // 8/9. loss
    loss_rows<<<B_, 256>>>(out);
    loss_reduce<<<1, 256>>>(mask, out);
    // 10/11. logits
    class_prep<<<1, 256>>>(mlr_a, mlr_p);
    logits_kernel<<<B_, 128>>>(out);
}

// round 13
// speedup vs baseline: 1.4685x; 1.4685x over previous
#include <cuda_runtime.h>
#include <cuda_bf16.h>
#include <math.h>
#include <stdint.h>

// ---------------- problem constants ----------------
constexpr int B_ = 4096;
constexpr int D_ = 1024;
constexpr int T_ = 768;
constexpr int C_ = 16;
constexpr int HD_ = 256;
constexpr float CURV = 0.05f;
constexpr float EPSF = 1e-8f;
constexpr float SCF = 0.22360679774997896f;
constexpr float ASINH_MAX = 11.090354888959125f;

constexpr size_t OFF_LOSS   = (size_t)B_ * C_;
constexpr size_t OFF_OH     = OFF_LOSS + 1;
constexpr size_t OFF_FH     = OFF_OH  + (size_t)B_ * D_;
constexpr size_t OFF_OEU    = OFF_FH  + (size_t)B_ * D_;
constexpr size_t OFF_FEU    = OFF_OEU + (size_t)B_ * D_;

// ---------------- device scratch ----------------
__device__ float g_gf   [(size_t)B_ * 4 * D_];
__device__ float g_qkv  [(size_t)B_ * 4 * 3 * D_];
__device__ float g_alin [(size_t)B_ * 4 * D_];
__device__ float g_oflin[(size_t)B_ * D_];
__device__ float g_fflin[(size_t)B_ * D_];
__device__ float g_peno [B_];
__device__ float g_penf [B_];
__device__ float g_clsx [C_ * D_];
__device__ float g_clsap[C_ * D_];
__device__ float g_clsx2[C_];
__device__ float g_clsax[C_];
__device__ float g_clsan[C_];
__device__ float g_clskk[C_];

__device__ __align__(16) __nv_bfloat16 g_gfh [(size_t)B_ * 4 * D_];
__device__ __align__(16) __nv_bfloat16 g_gfl [(size_t)B_ * 4 * D_];
__device__ __align__(16) __nv_bfloat16 g_aoh [(size_t)B_ * 4 * D_];
__device__ __align__(16) __nv_bfloat16 g_aol [(size_t)B_ * 4 * D_];
__device__ __align__(16) __nv_bfloat16 g_wih [(size_t)3 * D_ * D_];
__device__ __align__(16) __nv_bfloat16 g_wil [(size_t)3 * D_ * D_];
__device__ __align__(16) __nv_bfloat16 g_woh [(size_t)D_ * D_];
__device__ __align__(16) __nv_bfloat16 g_wol [(size_t)D_ * D_];
__device__ __align__(16) __nv_bfloat16 g_toh [(size_t)D_ * T_];
__device__ __align__(16) __nv_bfloat16 g_tol [(size_t)D_ * T_];
__device__ __align__(16) __nv_bfloat16 g_tfh [(size_t)D_ * T_];
__device__ __align__(16) __nv_bfloat16 g_tfl [(size_t)D_ * T_];
__device__ __align__(16) __nv_bfloat16 g_ordh[(size_t)B_ * T_];
__device__ __align__(16) __nv_bfloat16 g_ordl[(size_t)B_ * T_];
__device__ __align__(16) __nv_bfloat16 g_famh[(size_t)B_ * T_];
__device__ __align__(16) __nv_bfloat16 g_faml[(size_t)B_ * T_];

// ================= PTX helpers (baseline PTX only) =================
__device__ __forceinline__ uint32_t smem_to_u32(const void* p) {
    uint32_t a;
    asm("{ .reg .u64 t; cvta.to.shared.u64 t, %1; cvt.u32.u64 %0, t; }" : "=r"(a) : "l"(p));
    return a;
}
#define SWIZ128(o) ((o) ^ (((o) >> 3) & 0x70))

#define CP_ASYNC16(dst, src) \
    asm volatile("cp.async.cg.shared.global [%0], [%1], 16;" :: "r"(dst), "l"(src) : "memory")
#define CP_COMMIT() asm volatile("cp.async.commit_group;" ::: "memory")
#define CP_WAIT2()  asm volatile("cp.async.wait_group 2;" ::: "memory")
#define CP_WAIT1()  asm volatile("cp.async.wait_group 1;" ::: "memory")
#define CP_WAIT0()  asm volatile("cp.async.wait_group 0;" ::: "memory")

#define LDMATRIX_X4(r0, r1, r2, r3, addr) \
    asm volatile("ldmatrix.sync.aligned.m8n8.x4.shared.b16 {%0,%1,%2,%3}, [%4];" \
                 : "=r"(r0), "=r"(r1), "=r"(r2), "=r"(r3) : "r"(addr))

#define MMA_BF16(c0, c1, c2, c3, a0, a1, a2, a3, b0, b1) \
    asm volatile("mma.sync.aligned.m16n8k16.row.col.f32.bf16.bf16.f32 " \
                 "{%0,%1,%2,%3}, {%4,%5,%6,%7}, {%8,%9}, {%0,%1,%2,%3};" \
                 : "+f"(c0), "+f"(c1), "+f"(c2), "+f"(c3) \
                 : "r"(a0), "r"(a1), "r"(a2), "r"(a3), "r"(b0), "r"(b1))

// ================= split-bf16 tensor-core GEMM (round-9 structure, 3-stage) =================
// C[M,N] = (Ahi+Alo)[M,K] @ ((Bhi+Blo)[N,K])^T + bias[N]   (lo*lo dropped)
constexpr int BM = 128, BN = 128, KC = 64;
constexpr int ATILE_B = BM * 128;           // 16 KB (BK=64 bf16 = 128B rows)
constexpr int STAGE_B = 2 * ATILE_B;        // A + B per stage = 32 KB
constexpr int NSTG = 3;                     // pipeline depth
constexpr int GEMM_SMEM = NSTG * STAGE_B;   // 96 KB

__global__ void __launch_bounds__(256, 2)
gemm_bf16x3(const __nv_bfloat16* __restrict__ Ahi, const __nv_bfloat16* __restrict__ Alo,
            const __nv_bfloat16* __restrict__ Bhi, const __nv_bfloat16* __restrict__ Blo,
            const float* __restrict__ bias, float* __restrict__ Cm,
            int M, int N, int K) {
    extern __shared__ char smem[];
    uint32_t sb = smem_to_u32(smem);
    int tid = threadIdx.x;
    int wid = tid >> 5;
    int lane = tid & 31;
    int wm = wid & 1;       // 2 warps in M  -> warp tile 64 rows
    int wn = wid >> 1;      // 4 warps in N  -> warp tile 32 cols
    int m0 = blockIdx.y * BM;
    int n0 = blockIdx.x * BN;
    int nkseg = K / KC;
    int nk = 3 * nkseg;

    float acc[4][4][4];
#pragma unroll
    for (int i = 0; i < 4; i++)
#pragma unroll
        for (int j = 0; j < 4; j++)
#pragma unroll
            for (int t = 0; t < 4; t++) acc[i][j][t] = 0.f;

    int lc = tid & 7;        // 16B chunk within 128B row
    int lr = tid >> 3;       // base row (0..31)

    auto load_tile = [&](int k, int stage) {
        int seg = k / nkseg;
        int kk = (k - seg * nkseg) * KC;
        const __nv_bfloat16* Ag = (seg == 1 ? Alo : Ahi) + (size_t)m0 * K + kk;
        const __nv_bfloat16* Bg = (seg == 2 ? Blo : Bhi) + (size_t)n0 * K + kk;
        uint32_t sA = sb + stage * STAGE_B;
        uint32_t sB = sA + ATILE_B;
#pragma unroll
        for (int j = 0; j < 4; j++) {
            int row = lr + j * 32;
            uint32_t off = SWIZ128(row * 128 + lc * 16);
            CP_ASYNC16(sA + off, Ag + (size_t)row * K + lc * 8);
            CP_ASYNC16(sB + off, Bg + (size_t)row * K + lc * 8);
        }
        CP_COMMIT();
    };

    load_tile(0, 0);
    if (nk > 1) load_tile(1, 1);

    int stage = 0;
    for (int k = 0; k < nk; k++) {
        if (k + 2 < nk) load_tile(k + 2, (k + 2) % NSTG);
        // outstanding groups: k (oldest), k+1, k+2 -> wait until k's load done
        if (k + 2 < nk)      CP_WAIT2();
        else if (k + 1 < nk) CP_WAIT1();
        else                 CP_WAIT0();
        __syncthreads();

        uint32_t sA = sb + stage * STAGE_B;
        uint32_t sB = sA + ATILE_B;
#pragma unroll
        for (int ks = 0; ks < 4; ks++) {
            int kb = ks * 32;   // k byte offset within 128B row (16 elems * 2B)
            uint32_t a[4][4];
#pragma unroll
            for (int mi = 0; mi < 4; mi++) {
                int row = wm * 64 + mi * 16 + (lane & 15);
                uint32_t off = SWIZ128(row * 128 + kb + (lane >> 4) * 16);
                LDMATRIX_X4(a[mi][0], a[mi][1], a[mi][2], a[mi][3], sA + off);
            }
            uint32_t bq[2][4];
#pragma unroll
            for (int nj2 = 0; nj2 < 2; nj2++) {
                int g = lane >> 3;
                int row = wn * 32 + nj2 * 16 + (g >> 1) * 8 + (lane & 7);
                uint32_t off = SWIZ128(row * 128 + kb + (g & 1) * 16);
                LDMATRIX_X4(bq[nj2][0], bq[nj2][1], bq[nj2][2], bq[nj2][3], sB + off);
            }
#pragma unroll
            for (int mi = 0; mi < 4; mi++)
#pragma unroll
                for (int nj = 0; nj < 4; nj++) {
                    uint32_t b0 = bq[nj >> 1][(nj & 1) * 2 + 0];
                    uint32_t b1 = bq[nj >> 1][(nj & 1) * 2 + 1];
                    MMA_BF16(acc[mi][nj][0], acc[mi][nj][1], acc[mi][nj][2], acc[mi][nj][3],
                             a[mi][0], a[mi][1], a[mi][2], a[mi][3], b0, b1);
                }
        }
        __syncthreads();
        if (++stage == NSTG) stage = 0;
    }

    // epilogue: registers -> global, add bias
#pragma unroll
    for (int mi = 0; mi < 4; mi++) {
        int m = m0 + wm * 64 + mi * 16 + (lane >> 2);
#pragma unroll
        for (int nj = 0; nj < 4; nj++) {
            int n = n0 + wn * 32 + nj * 8 + (lane & 3) * 2;
            float2 bv = *(const float2*)(bias + n);
            float2 o0 = { acc[mi][nj][0] + bv.x, acc[mi][nj][1] + bv.y };
            float2 o1 = { acc[mi][nj][2] + bv.x, acc[mi][nj][3] + bv.y };
            *(float2*)(Cm + (size_t)m * N + n)       = o0;
            *(float2*)(Cm + (size_t)(m + 8) * N + n) = o1;
        }
    }
}

// ================= helpers =================
__device__ __forceinline__ float blockReduceSum(float v) {
    __shared__ float sh[33];
    int lane = threadIdx.x & 31;
    int wid  = threadIdx.x >> 5;
    __syncthreads();
#pragma unroll
    for (int o = 16; o; o >>= 1) v += __shfl_xor_sync(0xffffffffu, v, o);
    if (lane == 0) sh[wid] = v;
    __syncthreads();
    if (wid == 0) {
        int nw = (blockDim.x + 31) >> 5;
        float x = (lane < nw) ? sh[lane] : 0.f;
#pragma unroll
        for (int o = 16; o; o >>= 1) x += __shfl_xor_sync(0xffffffffu, x, o);
        if (lane == 0) sh[32] = x;
    }
    __syncthreads();
    return sh[32];
}
__device__ __forceinline__ float artanh_f(float x) {
    x = fminf(fmaxf(x, -1.f + 1e-5f), 1.f - 1e-5f);
    return 0.5f * (log1pf(x) - log1pf(-x));
}
__device__ __forceinline__ float plog_scale(float n) {
    n = fmaxf(n, 1e-15f);
    return artanh_f(SCF * n) / (n * SCF);
}
__device__ __forceinline__ float lexp_scale(float norm) {
    float rc = SCF * norm;
    float si = fminf(fmaxf(rc, EPSF), ASINH_MAX);
    return sinhf(si) / fmaxf(rc, EPSF);
}
__device__ __forceinline__ float oxy_angle_s(float xx, float nx, float xy, float yy) {
    float xt = sqrtf(1.f / CURV + xx);
    float yt = sqrtf(1.f / CURV + yy);
    float cxyl = CURV * (xy - xt * yt);
    float num = yt + cxyl * xt;
    float den = sqrtf(fmaxf(cxyl * cxyl - 1.f, EPSF));
    float ai = num / (nx * den + EPSF);
    ai = fminf(fmaxf(ai, -1.f + EPSF), 1.f - EPSF);
    return acosf(ai);
}
__device__ __forceinline__ float half_aperture_s(float nx) {
    float si = 0.2f / (nx * SCF + EPSF);
    si = fminf(fmaxf(si, -1.f + EPSF), 1.f - EPSF);
    return asinf(si);
}
__device__ __forceinline__ void bf16_split(float v, __nv_bfloat16* hi, __nv_bfloat16* lo, size_t i) {
    __nv_bfloat16 h = __float2bfloat16(v);
    hi[i] = h;
    lo[i] = __float2bfloat16(v - __bfloat162float(h));
}

// ---------------- prep_gf ----------------
__global__ void prep_gf(const float* __restrict__ ohyp, const float* __restrict__ fhyp,
                        const float* __restrict__ oeuc, const float* __restrict__ feuc) {
    int b = blockIdx.x;
    const float* xo = ohyp + (size_t)b * D_;
    const float* xf = fhyp + (size_t)b * D_;
    float so = 0.f, sf = 0.f;
    for (int i = threadIdx.x; i < D_; i += blockDim.x) {
        float a = xo[i]; so += a * a;
        float c = xf[i]; sf += c * c;
    }
    so = blockReduceSum(so);
    sf = blockReduceSum(sf);
    float to = plog_scale(sqrtf(so));
    float tf = plog_scale(sqrtf(sf));
    size_t rb = (size_t)b * 4 * D_;
    float* g0 = g_gf + rb;
    for (int i = threadIdx.x; i < D_; i += blockDim.x) {
        float v0 = xo[i] * to;
        float v1 = xf[i] * tf;
        float v2 = oeuc[(size_t)b * D_ + i];
        float v3 = feuc[(size_t)b * D_ + i];
        g0[i] = v0;  g0[D_ + i] = v1;  g0[2 * D_ + i] = v2;  g0[3 * D_ + i] = v3;
        bf16_split(v0, g_gfh, g_gfl, rb + i);
        bf16_split(v1, g_gfh, g_gfl, rb + D_ + i);
        bf16_split(v2, g_gfh, g_gfl, rb + 2 * D_ + i);
        bf16_split(v3, g_gfh, g_gfl, rb + 3 * D_ + i);
    }
}

// ---------------- fp32 -> bf16 hi/lo split ----------------
__global__ void cvt_split(const float* __restrict__ x, __nv_bfloat16* __restrict__ hi,
                          __nv_bfloat16* __restrict__ lo, int n4) {
    int i = blockIdx.x * blockDim.x + threadIdx.x;
    if (i < n4) {
        float4 v = *(const float4*)(x + (size_t)i * 4);
        size_t o = (size_t)i * 4;
        bf16_split(v.x, hi, lo, o + 0);
        bf16_split(v.y, hi, lo, o + 1);
        bf16_split(v.z, hi, lo, o + 2);
        bf16_split(v.w, hi, lo, o + 3);
    }
}

// ---------------- attention (S=4, one warp per head) ----------------
__global__ void attn_kernel() {
    int b = blockIdx.x;
    int hh = threadIdx.x >> 5;
    int lane = threadIdx.x & 31;
    const float* base = g_qkv + (size_t)b * 4 * (3 * D_);
    float s[4][4];
#pragma unroll
    for (int i = 0; i < 4; i++) {
#pragma unroll
        for (int j = 0; j < 4; j++) {
            const float* q = base + i * 3 * D_ + hh * HD_;
            const float* k = base + j * 3 * D_ + D_ + hh * HD_;
            float p = 0.f;
#pragma unroll
            for (int d = 0; d < HD_; d += 32) p += q[d + lane] * k[d + lane];
#pragma unroll
            for (int o = 16; o; o >>= 1) p += __shfl_xor_sync(0xffffffffu, p, o);
            s[i][j] = p * (1.f / 16.f);
        }
    }
    float a[4][4];
#pragma unroll
    for (int i = 0; i < 4; i++) {
        float m = fmaxf(fmaxf(s[i][0], s[i][1]), fmaxf(s[i][2], s[i][3]));
        float e0 = expf(s[i][0] - m), e1 = expf(s[i][1] - m);
        float e2 = expf(s[i][2] - m), e3 = expf(s[i][3] - m);
        float inv = 1.f / (e0 + e1 + e2 + e3);
        a[i][0] = e0 * inv; a[i][1] = e1 * inv; a[i][2] = e2 * inv; a[i][3] = e3 * inv;
    }
#pragma unroll
    for (int i = 0; i < 4; i++) {
        for (int d = lane; d < HD_; d += 32) {
            float acc = 0.f;
#pragma unroll
            for (int j = 0; j < 4; j++)
                acc += a[i][j] * base[j * 3 * D_ + 2 * D_ + hh * HD_ + d];
            bf16_split(acc, g_aoh, g_aol, (size_t)b * 4 * D_ + i * D_ + hh * HD_ + d);
        }
    }
}

// ---------------- residual + LN + l_expmap0 ----------------
__global__ void resid_ln_exp(const float* __restrict__ lnw, const float* __restrict__ lnb,
                             float* __restrict__ out) {
    int r = blockIdx.x;
    int b = r >> 2;
    int i = r & 3;
    const float* x0 = g_gf + (size_t)r * D_;
    const float* x1 = g_alin + (size_t)r * D_;
    float x[4];
    float s = 0.f;
#pragma unroll
    for (int t = 0; t < 4; t++) {
        int idx = threadIdx.x + t * 256;
        float v = x0[idx] + x1[idx];
        x[t] = v; s += v;
    }
    s = blockReduceSum(s);
    float mu = s * (1.f / D_);
    float vv = 0.f;
#pragma unroll
    for (int t = 0; t < 4; t++) { float d = x[t] - mu; vv += d * d; }
    vv = blockReduceSum(vv);
    float rstd = rsqrtf(vv * (1.f / D_) + 1e-5f);
    float y[4];
    float sy2 = 0.f;
#pragma unroll
    for (int t = 0; t < 4; t++) {
        int idx = threadIdx.x + t * 256;
        y[t] = (x[t] - mu) * rstd * lnw[idx] + lnb[idx];
        sy2 += y[t] * y[t];
    }
    if (i >= 2) {
        size_t off = (i == 2 ? OFF_OEU : OFF_FEU) + (size_t)b * D_;
#pragma unroll
        for (int t = 0; t < 4; t++) out[off + threadIdx.x + t * 256] = y[t];
    } else {
        sy2 = blockReduceSum(sy2);
        float sc = lexp_scale(sqrtf(sy2));
        size_t off = (i == 0 ? OFF_OH : OFF_FH) + (size_t)b * D_;
#pragma unroll
        for (int t = 0; t < 4; t++) out[off + threadIdx.x + t * 256] = y[t] * sc;
    }
}

// ---------------- per-row hyperbolic penalties ----------------
__global__ void loss_rows(const float* __restrict__ out) {
    int b = blockIdx.x;
    const float* of = g_oflin + (size_t)b * D_;
    const float* ff = g_fflin + (size_t)b * D_;
    const float* fh = out + OFF_FH + (size_t)b * D_;
    const float* oh = out + OFF_OH + (size_t)b * D_;
    float n2of = 0.f, dof = 0.f, n2fh = 0.f, n2ff = 0.f, dff = 0.f, n2oh = 0.f;
    for (int i = threadIdx.x; i < D_; i += blockDim.x) {
        float a = of[i], c = ff[i], yf = fh[i], yo = oh[i];
        n2of += a * a;  dof += a * yf;  n2fh += yf * yf;
        n2ff += c * c;  dff += c * yo;  n2oh += yo * yo;
    }
    n2of = blockReduceSum(n2of); dof = blockReduceSum(dof); n2fh = blockReduceSum(n2fh);
    n2ff = blockReduceSum(n2ff); dff = blockReduceSum(dff); n2oh = blockReduceSum(n2oh);
    if (threadIdx.x == 0) {
        float no = sqrtf(n2of);
        float so = lexp_scale(no);
        float xx = so * so * n2of, nx = so * no, xy = so * dof;
        float pen_o = fmaxf(oxy_angle_s(xx, nx, xy, n2fh) - half_aperture_s(nx), 0.f);
        float nf = sqrtf(n2ff);
        float sf = lexp_scale(nf);
        float xx2 = sf * sf * n2ff, nx2 = sf * nf, xy2 = sf * dff;
        float pen_f = fmaxf(oxy_angle_s(xx2, nx2, xy2, n2oh) - half_aperture_s(nx2), 0.f);
        g_peno[b] = pen_o;
        g_penf[b] = pen_f;
    }
}

__global__ void loss_reduce(const int* __restrict__ mask, float* __restrict__ out) {
    float so = 0.f, sf = 0.f, sm = 0.f;
    for (int i = threadIdx.x; i < B_; i += blockDim.x) {
        so += g_peno[i];
        float m = (float)mask[i];
        sf += g_penf[i] * m;
        sm += m;
    }
    so = blockReduceSum(so);
    sf = blockReduceSum(sf);
    sm = blockReduceSum(sm);
    if (threadIdx.x == 0) {
        float fam = (sm > 0.f) ? sf / fmaxf(sm, 1.f) : 0.f;
        out[OFF_LOSS] = so * (1.f / B_) + fam;
    }
}

// ---------------- per-class MLR constants ----------------
__global__ void class_prep(const float* __restrict__ mlr_a, const float* __restrict__ mlr_p) {
    for (int c = 0; c < C_; c++) {
        const float* p = mlr_p + (size_t)c * D_;
        const float* a = mlr_a + (size_t)c * D_;
        float n2p = 0.f, n2a = 0.f, dpa = 0.f;
        for (int i = threadIdx.x; i < D_; i += blockDim.x) {
            float pv = p[i], av = a[i];
            n2p += pv * pv; n2a += av * av; dpa += pv * av;
        }
        n2p = blockReduceSum(n2p);
        n2a = blockReduceSum(n2a);
        dpa = blockReduceSum(dpa);
        float n = fmaxf(sqrtf(n2p), 1e-15f);
        float t = tanhf(SCF * n) / (SCF * n);
        float pp2 = t * t * n2p;
        float conf = 1.f - CURV * pp2;
        float anorm = fabsf(conf) * sqrtf(n2a);
        float lam = 2.f / (1.f - CURV * pp2);
        if (threadIdx.x == 0) {
            g_clsx2[c] = pp2;
            g_clsax[c] = -t * conf * dpa;
            g_clsan[c] = anorm;
            g_clskk[c] = lam * anorm / SCF;
        }
        for (int i = threadIdx.x; i < D_; i += blockDim.x) {
            g_clsx[c * D_ + i]  = -t * p[i];
            g_clsap[c * D_ + i] = conf * a[i];
        }
    }
}

// ---------------- logits (closed-form mobius) ----------------
__global__ void logits_kernel(float* __restrict__ out) {
    int b = blockIdx.x;
    const float* oh = out + OFF_OH + (size_t)b * D_;
    float n2 = 0.f;
    float dx[C_], da[C_];
#pragma unroll
    for (int c = 0; c < C_; c++) { dx[c] = 0.f; da[c] = 0.f; }
    for (int i = threadIdx.x; i < D_; i += blockDim.x) {
        float v = oh[i];
        n2 += v * v;
#pragma unroll
        for (int c = 0; c < C_; c++) {
            dx[c] += v * g_clsx[c * D_ + i];
            da[c] += v * g_clsap[c * D_ + i];
        }
    }
    __shared__ float sred[33];
#pragma unroll
    for (int c = 0; c < C_; c++) {
        float r = blockReduceSum(dx[c]);
        if (threadIdx.x == 0) sred[c] = r;
    }
#pragma unroll
    for (int c = 0; c < C_; c++) {
        float r = blockReduceSum(da[c]);
        if (threadIdx.x == 0) sred[C_ + c] = r;
    }
    n2 = blockReduceSum(n2);
    if (threadIdx.x == 0) sred[32] = n2;
    __syncthreads();

    if (threadIdx.x < C_) {
        int c = threadIdx.x;
        float n2o = sred[32];
        float no = sqrtf(n2o);
        float rc1 = SCF * no;
        float t1 = asinhf(rc1) / fmaxf(rc1, EPSF);
        float nu = t1 * no;
        float ncl = fmaxf(nu, 1e-15f);
        float t2 = tanhf(SCF * ncl) / (SCF * ncl);
        float nxv = t2 * nu;
        float maxn = (1.f - 0.004f) / SCF;
        float proj = (nxv > maxn) ? maxn / fmaxf(nxv, 1e-15f) : 1.f;
        float g = t1 * t2 * proj;

        float y2 = g * g * n2o;
        float xy = g * sred[c];
        float ay = g * sred[C_ + c];
        float x2 = g_clsx2[c];
        float alpha = 1.f + 2.f * CURV * xy + CURV * y2;
        float beta  = 1.f - CURV * x2;
        float den0  = 1.f + 2.f * CURV * xy + CURV * CURV * x2 * y2 + 1e-5f;
        float mobdot = (alpha * g_clsax[c] + beta * ay) / den0;
        float mob2   = (alpha * alpha * x2 + 2.f * alpha * beta * xy + beta * beta * y2) / (den0 * den0);
        float num = 2.f * SCF * mobdot;
        float den = g_clsan[c] * (1.f - CURV * mob2);
        out[(size_t)b * C_ + c] = g_clskk[c] * asinhf(num / den);
    }
}

// ---------------- launch ----------------
extern "C" void kernel_launch(void* const* d_in, const int* in_sizes, int n_in,
                              void* d_out, int out_size) {
    const float* order_hyp  = (const float*)d_in[0];
    const float* family_hyp = (const float*)d_in[1];
    const float* order_euc  = (const float*)d_in[2];
    const float* family_euc = (const float*)d_in[3];
    const float* order      = (const float*)d_in[4];
    const float* family     = (const float*)d_in[5];
    const int*   mask       = (const int*)d_in[6];
    const float* in_proj_w  = (const float*)d_in[7];
    const float* in_proj_b  = (const float*)d_in[8];
    const float* out_proj_w = (const float*)d_in[9];
    const float* out_proj_b = (const float*)d_in[10];
    const float* ln_w       = (const float*)d_in[11];
    const float* ln_b       = (const float*)d_in[12];
    const float* to_w       = (const float*)d_in[13];
    const float* to_b       = (const float*)d_in[14];
    const float* tf_w       = (const float*)d_in[15];
    const float* tf_b       = (const float*)d_in[16];
    const float* mlr_a      = (const float*)d_in[17];
    const float* mlr_p      = (const float*)d_in[18];
    float* out = (float*)d_out;

    float* qkv  = nullptr; cudaGetSymbolAddress((void**)&qkv,  g_qkv);
    float* alin = nullptr; cudaGetSymbolAddress((void**)&alin, g_alin);
    float* ofl  = nullptr; cudaGetSymbolAddress((void**)&ofl,  g_oflin);
    float* ffl  = nullptr; cudaGetSymbolAddress((void**)&ffl,  g_fflin);
    __nv_bfloat16 *gfh, *gfl, *aoh, *aol, *wih, *wil, *woh, *wol;
    __nv_bfloat16 *toh, *tol, *tfh, *tfl, *ordh, *ordl, *famh, *faml;
    cudaGetSymbolAddress((void**)&gfh,  g_gfh);  cudaGetSymbolAddress((void**)&gfl,  g_gfl);
    cudaGetSymbolAddress((void**)&aoh,  g_aoh);  cudaGetSymbolAddress((void**)&aol,  g_aol);
    cudaGetSymbolAddress((void**)&wih,  g_wih);  cudaGetSymbolAddress((void**)&wil,  g_wil);
    cudaGetSymbolAddress((void**)&woh,  g_woh);  cudaGetSymbolAddress((void**)&wol,  g_wol);
    cudaGetSymbolAddress((void**)&toh,  g_toh);  cudaGetSymbolAddress((void**)&tol,  g_tol);
    cudaGetSymbolAddress((void**)&tfh,  g_tfh);  cudaGetSymbolAddress((void**)&tfl,  g_tfl);
    cudaGetSymbolAddress((void**)&ordh, g_ordh); cudaGetSymbolAddress((void**)&ordl, g_ordl);
    cudaGetSymbolAddress((void**)&famh, g_famh); cudaGetSymbolAddress((void**)&faml, g_faml);

    cudaFuncSetAttribute(gemm_bf16x3, cudaFuncAttributeMaxDynamicSharedMemorySize, GEMM_SMEM);

    auto splitN = [&](const float* src, __nv_bfloat16* hi, __nv_bfloat16* lo, size_t n) {
        int n4 = (int)(n / 4);
        cvt_split<<<(n4 + 255) / 256, 256>>>(src, hi, lo, n4);
    };
    splitN(in_proj_w,  wih,  wil,  (size_t)3 * D_ * D_);
    splitN(out_proj_w, woh,  wol,  (size_t)D_ * D_);
    splitN(to_w,       toh,  tol,  (size_t)D_ * T_);
    splitN(tf_w,       tfh,  tfl,  (size_t)D_ * T_);
    splitN(order,      ordh, ordl, (size_t)B_ * T_);
    splitN(family,     famh, faml, (size_t)B_ * T_);

    // 1. build gf (fp32 + bf16 split)
    prep_gf<<<B_, 256>>>(order_hyp, family_hyp, order_euc, family_euc);
    // 2. qkv = gf @ Win^T + b  [16384 x 3072, K=1024]
    gemm_bf16x3<<<dim3(3 * D_ / BN, B_ * 4 / BM), 256, GEMM_SMEM>>>(
        gfh, gfl, wih, wil, in_proj_b, qkv, B_ * 4, 3 * D_, D_);
    // 3. attention (writes bf16-split attn output)
    attn_kernel<<<B_, 128>>>();
    // 4. out-proj [16384 x 1024, K=1024]
    gemm_bf16x3<<<dim3(D_ / BN, B_ * 4 / BM), 256, GEMM_SMEM>>>(
        aoh, aol, woh, wol, out_proj_b, alin, B_ * 4, D_, D_);
    // 5. residual + LN + l_expmap0 -> outputs
    resid_ln_exp<<<B_ * 4, 256>>>(ln_w, ln_b, out);
    // 6/7. feature projections [4096 x 1024, K=768]
    gemm_bf16x3<<<dim3(D_ / BN, B_ / BM), 256, GEMM_SMEM>>>(
        ordh, ordl, toh, tol, to_b, ofl, B_, D_, T_);
    gemm_bf16x3<<<dim3(D_ / BN, B_ / BM), 256, GEMM_SMEM>>>(
        famh, faml, tfh, tfl, tf_b, ffl, B_, D_, T_);
    // 8/9. loss
    loss_rows<<<B_, 256>>>(out);
    loss_reduce<<<1, 256>>>(mask, out);
    // 10/11. logits
    class_prep<<<1, 256>>>(mlr_a, mlr_p);
    logits_kernel<<<B_, 128>>>(out);
}